// round 12
// baseline (speedup 1.0000x reference)
#include <cuda_runtime.h>
#include <cuda_bf16.h>

#define FEAT 1024
#define NREF 4
#define WPB 8            // warps per block
#define TPB (WPB * 32)
#define ROWS_PER_BLOCK (WPB * 2)

// 256-bit streaming global load/store (sm_100+: LDG.E.256 / STG.E.256).
__device__ __forceinline__ void ldg256_cs(const float* p, float4& a, float4& b) {
    asm volatile("ld.global.cs.v8.f32 {%0,%1,%2,%3,%4,%5,%6,%7}, [%8];"
                 : "=f"(a.x), "=f"(a.y), "=f"(a.z), "=f"(a.w),
                   "=f"(b.x), "=f"(b.y), "=f"(b.z), "=f"(b.w)
                 : "l"(p));
}
__device__ __forceinline__ void stg256_cs(float* p, const float4& a, const float4& b) {
    asm volatile("st.global.cs.v8.f32 [%0], {%1,%2,%3,%4,%5,%6,%7,%8};"
                 :: "l"(p),
                    "f"(a.x), "f"(a.y), "f"(a.z), "f"(a.w),
                    "f"(b.x), "f"(b.y), "f"(b.z), "f"(b.w)
                 : "memory");
}

// Fused single kernel (R11 structure): stage RAW vectors to SMEM + fold
// normalization into s = (-2/||v||^2) * dot. Body: 2 rows/warp, sequential
// reflections, shared v regs, interleaved butterflies. Global I/O now 256-bit:
// each lane owns a contiguous 32B chunk; a warp covers 1024B per request.
__global__ __launch_bounds__(TPB, 2) void householder_apply_kernel(
    const float* __restrict__ x, const float* __restrict__ vecs,
    float* __restrict__ out, int batch) {
    __shared__ float sv[NREF][FEAT];     // raw (unnormalized) vectors
    __shared__ float s_nred[NREF][WPB];  // per-warp ||v||^2 partials
    __shared__ float s_scale[NREF];      // -2 / ||v||^2

    int tid = threadIdx.x;
    int warp = tid >> 5;
    int lane = tid & 31;

    // ---- Stage vectors to SMEM and compute -2/||v||^2 in the same pass ----
    {
        float ss[NREF];
#pragma unroll
        for (int k = 0; k < NREF; k++) {
            float4 r = ((const float4*)(vecs + k * FEAT))[tid];  // 256 f4/vector
            ((float4*)sv[k])[tid] = r;
            ss[k] = r.x * r.x + r.y * r.y + r.z * r.z + r.w * r.w;
        }
#pragma unroll
        for (int o = 16; o; o >>= 1)
#pragma unroll
            for (int k = 0; k < NREF; k++) ss[k] += __shfl_xor_sync(0xffffffffu, ss[k], o);
        if (lane == 0)
#pragma unroll
            for (int k = 0; k < NREF; k++) s_nred[k][warp] = ss[k];
        __syncthreads();
        if (tid < NREF) {
            float tot = 0.f;
#pragma unroll
            for (int w = 0; w < WPB; w++) tot += s_nred[tid][w];
            s_scale[tid] = -2.f / tot;
        }
        __syncthreads();
    }

    float scale[NREF];
#pragma unroll
    for (int k = 0; k < NREF; k++) scale[k] = s_scale[k];

    long long rowA = (long long)blockIdx.x * ROWS_PER_BLOCK + warp;
    long long rowB = rowA + WPB;
    bool hasA = rowA < batch;
    bool hasB = rowB < batch;

    // Each lane owns 4 chunks of 8 contiguous floats: offset c*256 + lane*8.
    const float* xa = x + rowA * (long long)FEAT;
    const float* xb = x + rowB * (long long)FEAT;
    float4 ya[8], yb[8];   // ya[2c],ya[2c+1] = chunk c
    if (hasA) {
#pragma unroll
        for (int c = 0; c < 4; c++)
            ldg256_cs(xa + c * 256 + lane * 8, ya[2 * c], ya[2 * c + 1]);
    }
    if (hasB) {
#pragma unroll
        for (int c = 0; c < 4; c++)
            ldg256_cs(xb + c * 256 + lane * 8, yb[2 * c], yb[2 * c + 1]);
    }

#pragma unroll
    for (int k = 0; k < NREF; k++) {
        const float4* vp = (const float4*)sv[k];
        float4 vv[8];
        float da = 0.f, db = 0.f;
#pragma unroll
        for (int c = 0; c < 4; c++) {
#pragma unroll
            for (int h = 0; h < 2; h++) {
                int j = 2 * c + h;
                vv[j] = vp[c * 64 + lane * 2 + h];  // matches chunk layout
                da = fmaf(ya[j].x, vv[j].x, da);
                da = fmaf(ya[j].y, vv[j].y, da);
                da = fmaf(ya[j].z, vv[j].z, da);
                da = fmaf(ya[j].w, vv[j].w, da);
                db = fmaf(yb[j].x, vv[j].x, db);
                db = fmaf(yb[j].y, vv[j].y, db);
                db = fmaf(yb[j].z, vv[j].z, db);
                db = fmaf(yb[j].w, vv[j].w, db);
            }
        }
        // Two independent butterflies, interleaved so latencies overlap.
#pragma unroll
        for (int o = 16; o; o >>= 1) {
            da += __shfl_xor_sync(0xffffffffu, da, o);
            db += __shfl_xor_sync(0xffffffffu, db, o);
        }
        float sa = scale[k] * da;
        float sb = scale[k] * db;
#pragma unroll
        for (int j = 0; j < 8; j++) {
            ya[j].x = fmaf(sa, vv[j].x, ya[j].x);
            ya[j].y = fmaf(sa, vv[j].y, ya[j].y);
            ya[j].z = fmaf(sa, vv[j].z, ya[j].z);
            ya[j].w = fmaf(sa, vv[j].w, ya[j].w);
            yb[j].x = fmaf(sb, vv[j].x, yb[j].x);
            yb[j].y = fmaf(sb, vv[j].y, yb[j].y);
            yb[j].z = fmaf(sb, vv[j].z, yb[j].z);
            yb[j].w = fmaf(sb, vv[j].w, yb[j].w);
        }
    }

    if (hasA) {
        float* oa = out + rowA * (long long)FEAT;
#pragma unroll
        for (int c = 0; c < 4; c++)
            stg256_cs(oa + c * 256 + lane * 8, ya[2 * c], ya[2 * c + 1]);
    }
    if (hasB) {
        float* ob = out + rowB * (long long)FEAT;
#pragma unroll
        for (int c = 0; c < 4; c++)
            stg256_cs(ob + c * 256 + lane * 8, yb[2 * c], yb[2 * c + 1]);
    }
}

extern "C" void kernel_launch(void* const* d_in, const int* in_sizes, int n_in,
                              void* d_out, int out_size) {
    const float* x = (const float*)d_in[0];       // (BATCH, 1024) fp32
    const float* vectors = (const float*)d_in[1]; // (4, 1024) fp32
    float* out = (float*)d_out;
    int batch = in_sizes[0] / FEAT;

    int blocks = (batch + ROWS_PER_BLOCK - 1) / ROWS_PER_BLOCK;
    householder_apply_kernel<<<blocks, TPB>>>(x, vectors, out, batch);
}

// round 13
// speedup vs baseline: 1.0317x; 1.0317x over previous
#include <cuda_runtime.h>
#include <cuda_bf16.h>

#define FEAT 1024
#define NREF 4
#define WPB 8            // warps per block
#define TPB (WPB * 32)
#define ROWS_PER_BLOCK (WPB * 2)

// Fused single kernel (R11-proven structure): stage RAW vectors into SMEM and
// fold normalization into the per-reflection scalar s = (-2/||v||^2) * dot.
// Body: 2 rows/warp, sequential reflections, v regs shared across rows,
// interleaved shfl butterflies. A/B this round: plain loads (no .cs hint),
// streaming stores (.cs).
__global__ __launch_bounds__(TPB, 2) void householder_apply_kernel(
    const float* __restrict__ x, const float* __restrict__ vecs,
    float* __restrict__ out, int batch) {
    __shared__ float sv[NREF][FEAT];     // raw (unnormalized) vectors
    __shared__ float s_nred[NREF][WPB];  // per-warp ||v||^2 partials
    __shared__ float s_scale[NREF];      // -2 / ||v||^2

    int tid = threadIdx.x;
    int warp = tid >> 5;
    int lane = tid & 31;

    // ---- Stage vectors to SMEM and compute -2/||v||^2 in the same pass ----
    {
        float ss[NREF];
#pragma unroll
        for (int k = 0; k < NREF; k++) {
            float4 r = ((const float4*)(vecs + k * FEAT))[tid];  // 256 f4/vector
            ((float4*)sv[k])[tid] = r;
            ss[k] = r.x * r.x + r.y * r.y + r.z * r.z + r.w * r.w;
        }
#pragma unroll
        for (int o = 16; o; o >>= 1)
#pragma unroll
            for (int k = 0; k < NREF; k++) ss[k] += __shfl_xor_sync(0xffffffffu, ss[k], o);
        if (lane == 0)
#pragma unroll
            for (int k = 0; k < NREF; k++) s_nred[k][warp] = ss[k];
        __syncthreads();
        if (tid < NREF) {
            float tot = 0.f;
#pragma unroll
            for (int w = 0; w < WPB; w++) tot += s_nred[tid][w];
            s_scale[tid] = -2.f / tot;
        }
        __syncthreads();
    }

    float scale[NREF];
#pragma unroll
    for (int k = 0; k < NREF; k++) scale[k] = s_scale[k];

    long long rowA = (long long)blockIdx.x * ROWS_PER_BLOCK + warp;
    long long rowB = rowA + WPB;
    bool hasA = rowA < batch;
    bool hasB = rowB < batch;

    const float4* xa = (const float4*)(x + rowA * (long long)FEAT);
    const float4* xb = (const float4*)(x + rowB * (long long)FEAT);
    float4 ya[8], yb[8];
    if (hasA) {
#pragma unroll
        for (int j = 0; j < 8; j++) ya[j] = xa[j * 32 + lane];
    }
    if (hasB) {
#pragma unroll
        for (int j = 0; j < 8; j++) yb[j] = xb[j * 32 + lane];
    }

#pragma unroll
    for (int k = 0; k < NREF; k++) {
        const float4* vp = (const float4*)sv[k];
        float4 vv[8];
        float da = 0.f, db = 0.f;
#pragma unroll
        for (int j = 0; j < 8; j++) {
            vv[j] = vp[j * 32 + lane];
            da = fmaf(ya[j].x, vv[j].x, da);
            da = fmaf(ya[j].y, vv[j].y, da);
            da = fmaf(ya[j].z, vv[j].z, da);
            da = fmaf(ya[j].w, vv[j].w, da);
            db = fmaf(yb[j].x, vv[j].x, db);
            db = fmaf(yb[j].y, vv[j].y, db);
            db = fmaf(yb[j].z, vv[j].z, db);
            db = fmaf(yb[j].w, vv[j].w, db);
        }
        // Two independent butterflies, interleaved so latencies overlap.
#pragma unroll
        for (int o = 16; o; o >>= 1) {
            da += __shfl_xor_sync(0xffffffffu, da, o);
            db += __shfl_xor_sync(0xffffffffu, db, o);
        }
        float sa = scale[k] * da;
        float sb = scale[k] * db;
#pragma unroll
        for (int j = 0; j < 8; j++) {
            ya[j].x = fmaf(sa, vv[j].x, ya[j].x);
            ya[j].y = fmaf(sa, vv[j].y, ya[j].y);
            ya[j].z = fmaf(sa, vv[j].z, ya[j].z);
            ya[j].w = fmaf(sa, vv[j].w, ya[j].w);
            yb[j].x = fmaf(sb, vv[j].x, yb[j].x);
            yb[j].y = fmaf(sb, vv[j].y, yb[j].y);
            yb[j].z = fmaf(sb, vv[j].z, yb[j].z);
            yb[j].w = fmaf(sb, vv[j].w, yb[j].w);
        }
    }

    if (hasA) {
        float4* oa = (float4*)(out + rowA * (long long)FEAT);
#pragma unroll
        for (int j = 0; j < 8; j++) __stcs(&oa[j * 32 + lane], ya[j]);
    }
    if (hasB) {
        float4* ob = (float4*)(out + rowB * (long long)FEAT);
#pragma unroll
        for (int j = 0; j < 8; j++) __stcs(&ob[j * 32 + lane], yb[j]);
    }
}

extern "C" void kernel_launch(void* const* d_in, const int* in_sizes, int n_in,
                              void* d_out, int out_size) {
    const float* x = (const float*)d_in[0];       // (BATCH, 1024) fp32
    const float* vectors = (const float*)d_in[1]; // (4, 1024) fp32
    float* out = (float*)d_out;
    int batch = in_sizes[0] / FEAT;

    int blocks = (batch + ROWS_PER_BLOCK - 1) / ROWS_PER_BLOCK;
    householder_apply_kernel<<<blocks, TPB>>>(x, vectors, out, batch);
}

// round 14
// speedup vs baseline: 1.0340x; 1.0023x over previous
#include <cuda_runtime.h>
#include <cuda_bf16.h>

#define FEAT 1024
#define NREF 4
#define WPB 8            // warps per block
#define TPB (WPB * 32)
#define ROWS_PER_BLOCK (WPB * 2)

// Fused single kernel (R13-proven structure): stage RAW vectors into SMEM and
// fold normalization into the per-reflection scalar s = (-2/||v||^2) * dot.
// Body: 2 rows/warp, sequential reflections, v regs shared across rows,
// interleaved shfl butterflies. A/B this round: plain stores (no .cs) —
// completing the hint matrix after plain loads won in R13.
__global__ __launch_bounds__(TPB, 2) void householder_apply_kernel(
    const float* __restrict__ x, const float* __restrict__ vecs,
    float* __restrict__ out, int batch) {
    __shared__ float sv[NREF][FEAT];     // raw (unnormalized) vectors
    __shared__ float s_nred[NREF][WPB];  // per-warp ||v||^2 partials
    __shared__ float s_scale[NREF];      // -2 / ||v||^2

    int tid = threadIdx.x;
    int warp = tid >> 5;
    int lane = tid & 31;

    // ---- Stage vectors to SMEM and compute -2/||v||^2 in the same pass ----
    {
        float ss[NREF];
#pragma unroll
        for (int k = 0; k < NREF; k++) {
            float4 r = ((const float4*)(vecs + k * FEAT))[tid];  // 256 f4/vector
            ((float4*)sv[k])[tid] = r;
            ss[k] = r.x * r.x + r.y * r.y + r.z * r.z + r.w * r.w;
        }
#pragma unroll
        for (int o = 16; o; o >>= 1)
#pragma unroll
            for (int k = 0; k < NREF; k++) ss[k] += __shfl_xor_sync(0xffffffffu, ss[k], o);
        if (lane == 0)
#pragma unroll
            for (int k = 0; k < NREF; k++) s_nred[k][warp] = ss[k];
        __syncthreads();
        if (tid < NREF) {
            float tot = 0.f;
#pragma unroll
            for (int w = 0; w < WPB; w++) tot += s_nred[tid][w];
            s_scale[tid] = -2.f / tot;
        }
        __syncthreads();
    }

    float scale[NREF];
#pragma unroll
    for (int k = 0; k < NREF; k++) scale[k] = s_scale[k];

    long long rowA = (long long)blockIdx.x * ROWS_PER_BLOCK + warp;
    long long rowB = rowA + WPB;
    bool hasA = rowA < batch;
    bool hasB = rowB < batch;

    const float4* xa = (const float4*)(x + rowA * (long long)FEAT);
    const float4* xb = (const float4*)(x + rowB * (long long)FEAT);
    float4 ya[8], yb[8];
    if (hasA) {
#pragma unroll
        for (int j = 0; j < 8; j++) ya[j] = xa[j * 32 + lane];
    }
    if (hasB) {
#pragma unroll
        for (int j = 0; j < 8; j++) yb[j] = xb[j * 32 + lane];
    }

#pragma unroll
    for (int k = 0; k < NREF; k++) {
        const float4* vp = (const float4*)sv[k];
        float4 vv[8];
        float da = 0.f, db = 0.f;
#pragma unroll
        for (int j = 0; j < 8; j++) {
            vv[j] = vp[j * 32 + lane];
            da = fmaf(ya[j].x, vv[j].x, da);
            da = fmaf(ya[j].y, vv[j].y, da);
            da = fmaf(ya[j].z, vv[j].z, da);
            da = fmaf(ya[j].w, vv[j].w, da);
            db = fmaf(yb[j].x, vv[j].x, db);
            db = fmaf(yb[j].y, vv[j].y, db);
            db = fmaf(yb[j].z, vv[j].z, db);
            db = fmaf(yb[j].w, vv[j].w, db);
        }
        // Two independent butterflies, interleaved so latencies overlap.
#pragma unroll
        for (int o = 16; o; o >>= 1) {
            da += __shfl_xor_sync(0xffffffffu, da, o);
            db += __shfl_xor_sync(0xffffffffu, db, o);
        }
        float sa = scale[k] * da;
        float sb = scale[k] * db;
#pragma unroll
        for (int j = 0; j < 8; j++) {
            ya[j].x = fmaf(sa, vv[j].x, ya[j].x);
            ya[j].y = fmaf(sa, vv[j].y, ya[j].y);
            ya[j].z = fmaf(sa, vv[j].z, ya[j].z);
            ya[j].w = fmaf(sa, vv[j].w, ya[j].w);
            yb[j].x = fmaf(sb, vv[j].x, yb[j].x);
            yb[j].y = fmaf(sb, vv[j].y, yb[j].y);
            yb[j].z = fmaf(sb, vv[j].z, yb[j].z);
            yb[j].w = fmaf(sb, vv[j].w, yb[j].w);
        }
    }

    if (hasA) {
        float4* oa = (float4*)(out + rowA * (long long)FEAT);
#pragma unroll
        for (int j = 0; j < 8; j++) oa[j * 32 + lane] = ya[j];
    }
    if (hasB) {
        float4* ob = (float4*)(out + rowB * (long long)FEAT);
#pragma unroll
        for (int j = 0; j < 8; j++) ob[j * 32 + lane] = yb[j];
    }
}

extern "C" void kernel_launch(void* const* d_in, const int* in_sizes, int n_in,
                              void* d_out, int out_size) {
    const float* x = (const float*)d_in[0];       // (BATCH, 1024) fp32
    const float* vectors = (const float*)d_in[1]; // (4, 1024) fp32
    float* out = (float*)d_out;
    int batch = in_sizes[0] / FEAT;

    int blocks = (batch + ROWS_PER_BLOCK - 1) / ROWS_PER_BLOCK;
    householder_apply_kernel<<<blocks, TPB>>>(x, vectors, out, batch);
}